// round 5
// baseline (speedup 1.0000x reference)
#include <cuda_runtime.h>
#include <cuda_bf16.h>
#include <cstdint>

#define NELEM 4194304          // 32*512*32*8 == 4*512*8*256
#define WSZ   2359296          // 512*4608 weight elements per conv

// ---------------------------------------------------------------------------
// device scratch
// ---------------------------------------------------------------------------
__device__ __nv_bfloat16 g_Bh[4*WSZ];   // weights hi  [conv][co][t*512+ci]
__device__ __nv_bfloat16 g_Bl[4*WSZ];   // weights lo
__device__ __nv_bfloat16 g_xh[3*NELEM]; // qkv inputs hi, pixel-major [z][n][p][ci]
__device__ __nv_bfloat16 g_xl[3*NELEM];
__device__ __nv_bfloat16 g_sah[NELEM];  // conv_o input hi [b][p][ci]
__device__ __nv_bfloat16 g_sal[NELEM];
__device__ float g_y0[NELEM];           // conv(q) out (32,512,32,8)
__device__ float g_y1[NELEM];
__device__ float g_y2[NELEM];
__device__ __nv_bfloat16 g_Qh[NELEM], g_Ql[NELEM];   // [n][d][c], c=h*32+r
__device__ __nv_bfloat16 g_Kh[NELEM], g_Kl[NELEM];
__device__ __nv_bfloat16 g_Vth[NELEM], g_Vtl[NELEM]; // transposed: [n][c][dk]
__device__ __nv_bfloat16 g_ath[2*NELEM], g_atl[2*NELEM]; // attn hi/lo
__device__ float g_On[NELEM];           // attn @ V  [n][qd][c]

// ---------------------------------------------------------------------------
// helpers
// ---------------------------------------------------------------------------
__device__ __forceinline__ uint32_t smem_u32(const void* p) {
    uint32_t a;
    asm("{ .reg .u64 t; cvta.to.shared.u64 t, %1; cvt.u32.u64 %0, t; }" : "=r"(a) : "l"(p));
    return a;
}
#define SWZ(o) ((o) ^ (((o) >> 3) & 0x70))
#define CPA(dst, src, sz) \
    asm volatile("cp.async.cg.shared.global [%0], [%1], 16, %2;" \
        :: "r"(dst), "l"(src), "r"(sz) : "memory")
#define CPA_COMMIT() asm volatile("cp.async.commit_group;" ::: "memory")
#define CPA_WAIT1()  asm volatile("cp.async.wait_group 1;" ::: "memory")
#define CPA_WAIT0()  asm volatile("cp.async.wait_group 0;" ::: "memory")
#define LDM4(r, addr) \
    asm volatile("ldmatrix.sync.aligned.m8n8.x4.shared.b16 {%0,%1,%2,%3}, [%4];" \
        : "=r"((r)[0]), "=r"((r)[1]), "=r"((r)[2]), "=r"((r)[3]) : "r"(addr))
#define MMA_BF16(d, a, b0, b1) \
    asm volatile("mma.sync.aligned.m16n8k16.row.col.f32.bf16.bf16.f32 " \
        "{%0,%1,%2,%3}, {%4,%5,%6,%7}, {%8,%9}, {%0,%1,%2,%3};" \
        : "+f"((d)[0]), "+f"((d)[1]), "+f"((d)[2]), "+f"((d)[3]) \
        : "r"((a)[0]), "r"((a)[1]), "r"((a)[2]), "r"((a)[3]), "r"(b0), "r"(b1))

#define SMEM_BYTES 196608
// conv: 2 stages x 96KB (Ah 0, Al 16K, Bh 32K, Bl 64K)
#define CSTAGE 98304u
// gemm: 3 stages x 64KB (Ah 0, Al 16K, Bh 32K, Bl 48K)
#define GSTAGE 65536u

// ---------------------------------------------------------------------------
// compute one K64 chunk, warp tile 64x64: D += Ah*Bh + Ah*Bl + Al*Bh
// ---------------------------------------------------------------------------
__device__ __forceinline__ void mma_compute64_w64(uint32_t bs, uint32_t a_rowb,
                                                  uint32_t b_rowb, float (&acc)[32][4])
{
#pragma unroll
    for (int s = 0; s < 4; ++s) {
        uint32_t ah[4][4], bb[4][4], blf[4][4];
#pragma unroll
        for (int i = 0; i < 4; ++i)
            LDM4(ah[i], bs + SWZ(a_rowb + i * 2048 + s * 32));
#pragma unroll
        for (int j = 0; j < 4; ++j)
            LDM4(bb[j], bs + 32768u + SWZ(b_rowb + j * 2048 + s * 32));
#pragma unroll
        for (int i = 0; i < 4; ++i)
#pragma unroll
            for (int jj = 0; jj < 8; ++jj)
                MMA_BF16(acc[i * 8 + jj], ah[i],
                         bb[jj >> 1][(jj & 1) * 2], bb[jj >> 1][(jj & 1) * 2 + 1]);
#pragma unroll
        for (int j = 0; j < 4; ++j)
            LDM4(blf[j], bs + 65536u + SWZ(b_rowb + j * 2048 + s * 32));
#pragma unroll
        for (int i = 0; i < 4; ++i)
#pragma unroll
            for (int jj = 0; jj < 8; ++jj)
                MMA_BF16(acc[i * 8 + jj], ah[i],
                         blf[jj >> 1][(jj & 1) * 2], blf[jj >> 1][(jj & 1) * 2 + 1]);
#pragma unroll
        for (int i = 0; i < 4; ++i)
            LDM4(ah[i], bs + 16384u + SWZ(a_rowb + i * 2048 + s * 32));
#pragma unroll
        for (int i = 0; i < 4; ++i)
#pragma unroll
            for (int jj = 0; jj < 8; ++jj)
                MMA_BF16(acc[i * 8 + jj], ah[i],
                         bb[jj >> 1][(jj & 1) * 2], bb[jj >> 1][(jj & 1) * 2 + 1]);
    }
}

// warp tile 64x32 (for attention GEMMs, 128x128 CTA tile)
__device__ __forceinline__ void mma_compute64(uint32_t bs, uint32_t a_rowb,
                                              uint32_t b_rowb, float (&acc)[16][4])
{
#pragma unroll
    for (int s = 0; s < 4; ++s) {
        uint32_t ah[4][4], bb[2][4], blf[2][4];
#pragma unroll
        for (int i = 0; i < 4; ++i)
            LDM4(ah[i], bs + SWZ(a_rowb + i * 2048 + s * 32));
#pragma unroll
        for (int j = 0; j < 2; ++j)
            LDM4(bb[j], bs + 32768u + SWZ(b_rowb + j * 2048 + s * 32));
#pragma unroll
        for (int i = 0; i < 4; ++i)
#pragma unroll
            for (int jj = 0; jj < 4; ++jj)
                MMA_BF16(acc[i * 4 + jj], ah[i],
                         bb[jj >> 1][(jj & 1) * 2], bb[jj >> 1][(jj & 1) * 2 + 1]);
#pragma unroll
        for (int j = 0; j < 2; ++j)
            LDM4(blf[j], bs + 49152u + SWZ(b_rowb + j * 2048 + s * 32));
#pragma unroll
        for (int i = 0; i < 4; ++i)
#pragma unroll
            for (int jj = 0; jj < 4; ++jj)
                MMA_BF16(acc[i * 4 + jj], ah[i],
                         blf[jj >> 1][(jj & 1) * 2], blf[jj >> 1][(jj & 1) * 2 + 1]);
#pragma unroll
        for (int i = 0; i < 4; ++i)
            LDM4(ah[i], bs + 16384u + SWZ(a_rowb + i * 2048 + s * 32));
#pragma unroll
        for (int i = 0; i < 4; ++i)
#pragma unroll
            for (int jj = 0; jj < 4; ++jj)
                MMA_BF16(acc[i * 4 + jj], ah[i],
                         bb[jj >> 1][(jj & 1) * 2], bb[jj >> 1][(jj & 1) * 2 + 1]);
    }
}

// ---------------------------------------------------------------------------
// pre-pass: weights -> bf16 hi/lo in [co][t*512+ci] layout
// ---------------------------------------------------------------------------
__global__ void prep_w(const float* __restrict__ Wq, const float* __restrict__ Wk,
                       const float* __restrict__ Wv, const float* __restrict__ Wo)
{
    int g = blockIdx.x * 256 + threadIdx.x;
    int conv = g / WSZ;
    int j = g - conv * WSZ;
    const float* W = (conv == 0) ? Wq : (conv == 1) ? Wk : (conv == 2) ? Wv : Wo;
    float v = W[j];
    int co  = j / 4608;
    int rem = j - co * 4608;
    int ci  = rem / 9;
    int t   = rem - ci * 9;
    __nv_bfloat16 h = __float2bfloat16(v);
    __nv_bfloat16 l = __float2bfloat16(v - __bfloat162float(h));
    size_t o = (size_t)conv * WSZ + (size_t)co * 4608 + t * 512 + ci;
    g_Bh[o] = h;
    g_Bl[o] = l;
}

// ---------------------------------------------------------------------------
// pre-pass: q/k/v (32 imgs, 512 ch, 256 pix) -> pixel-major bf16 hi/lo
// ---------------------------------------------------------------------------
__global__ void prep_x(const float* __restrict__ q, const float* __restrict__ k,
                       const float* __restrict__ v, int zoff)
{
    __shared__ float tile[32][33];
    int zz = blockIdx.z + zoff;
    int z = zz >> 5;
    int n = zz & 31;
    const float* src = (z == 0) ? q : (z == 1) ? k : v;
    const float* xin = src + (size_t)n * 512 * 256;
    __nv_bfloat16* oh = g_xh + (size_t)z * NELEM + (size_t)n * 256 * 512;
    __nv_bfloat16* ol = g_xl + (size_t)z * NELEM + (size_t)n * 256 * 512;
    int p0 = blockIdx.x * 32;
    int c0 = blockIdx.y * 32;
    int tx = threadIdx.x, ty = threadIdx.y;
#pragma unroll
    for (int j = 0; j < 4; ++j)
        tile[ty + 8 * j][tx] = xin[(size_t)(c0 + ty + 8 * j) * 256 + p0 + tx];
    __syncthreads();
#pragma unroll
    for (int j = 0; j < 4; ++j) {
        float val = tile[tx][ty + 8 * j];
        __nv_bfloat16 h = __float2bfloat16(val);
        size_t o = (size_t)(p0 + ty + 8 * j) * 512 + c0 + tx;
        oh[o] = h;
        ol[o] = __float2bfloat16(val - __bfloat162float(h));
    }
}

// ---------------------------------------------------------------------------
// 2-stage cp.async pipelined implicit-GEMM conv. M=128 pix x N=256 co.
// 8 warps (2 x 4), warp tile 64x64. K in 72 chunks of 64 (tap-major).
// ---------------------------------------------------------------------------
__device__ __forceinline__ void conv_mma_pipe(
    const __nv_bfloat16* __restrict__ xh, const __nv_bfloat16* __restrict__ xl,
    const __nv_bfloat16* __restrict__ bh, const __nv_bfloat16* __restrict__ bl,
    const float* __restrict__ bias, float* __restrict__ y,
    int H, int W, int logW, int logPIX)
{
    extern __shared__ char smem[];
    uint32_t sb = smem_u32(smem);
    int tid = threadIdx.x, wid = tid >> 5, lane = tid & 31;
    const int HW = 1 << logPIX;
    int p0    = blockIdx.x * 128;
    int nimg  = p0 >> logPIX;
    int pbase = p0 & (HW - 1);
    int co0   = blockIdx.y * 256;
    int wm = wid & 1, wn = wid >> 1;

    // A loader: thread -> (pixel row, 64B half)
    int ar = tid >> 1, aseg = tid & 1;
    int ap = pbase + ar;
    int ayr = ap >> logW, axr = ap & (W - 1);
    uint32_t arawb = (uint32_t)(ar * 128 + aseg * 64);
    const __nv_bfloat16* arow_h = xh + (size_t)nimg * HW * 512 + aseg * 32;
    const __nv_bfloat16* arow_l = xl + (size_t)nimg * HW * 512 + aseg * 32;
    // B loader: thread -> full 128B cout row
    uint32_t brawb = (uint32_t)(tid * 128);
    const __nv_bfloat16* brow_h = bh + (size_t)(co0 + tid) * 4608;
    const __nv_bfloat16* brow_l = bl + (size_t)(co0 + tid) * 4608;

    uint32_t a_rowb = (uint32_t)((wm * 64 + (lane & 15)) * 128) + ((lane & 16) ? 16u : 0u);
    uint32_t b_rowb = (uint32_t)((wn * 64 + (lane & 7) + ((lane & 16) ? 8 : 0)) * 128)
                    + ((lane & 8) ? 16u : 0u);

    float acc[32][4];
#pragma unroll
    for (int i = 0; i < 32; ++i)
#pragma unroll
        for (int j = 0; j < 4; ++j) acc[i][j] = 0.f;

    auto prefetch = [&](int itn, int stg) {
        int t = itn >> 3, ci0 = (itn & 7) << 6;
        int q3 = (t * 11) >> 5;                 // t/3 for t in [0,9)
        int dy = q3 - 1, dx = t - q3 * 3 - 1;
        int yy = ayr + dy, xx = axr + dx;
        bool ok = ((unsigned)yy < (unsigned)H) && ((unsigned)xx < (unsigned)W);
        int pps = ok ? ((yy << logW) + xx) : 0;
        const char* sAh = (const char*)(arow_h + (size_t)pps * 512 + ci0);
        const char* sAl = (const char*)(arow_l + (size_t)pps * 512 + ci0);
        const char* sBh = (const char*)(brow_h + t * 512 + ci0);
        const char* sBl = (const char*)(brow_l + t * 512 + ci0);
        uint32_t bs = sb + (uint32_t)stg * CSTAGE;
        uint32_t asz = ok ? 16u : 0u;
#pragma unroll
        for (int j = 0; j < 4; ++j) {
            uint32_t sw = SWZ(arawb + j * 16);
            CPA(bs + sw,          sAh + j * 16, asz);
            CPA(bs + 16384u + sw, sAl + j * 16, asz);
        }
#pragma unroll
        for (int j = 0; j < 8; ++j) {
            uint32_t sw = SWZ(brawb + j * 16);
            CPA(bs + 32768u + sw, sBh + j * 16, 16u);
            CPA(bs + 65536u + sw, sBl + j * 16, 16u);
        }
        CPA_COMMIT();
    };

    prefetch(0, 0);
    for (int it = 0; it < 72; ++it) {
        CPA_WAIT0();
        __syncthreads();
        if (it + 1 < 72) prefetch(it + 1, (it + 1) & 1);
        mma_compute64_w64(sb + (uint32_t)(it & 1) * CSTAGE, a_rowb, b_rowb, acc);
    }

    // epilogue: two 128-col passes staged via SMEM for coalesced stores
    float* sf = (float*)smem;
#pragma unroll
    for (int pass = 0; pass < 2; ++pass) {
        __syncthreads();
        if ((wn >> 1) == pass) {
            int wnl = wn & 1;
#pragma unroll
            for (int i = 0; i < 4; ++i) {
                int row = wm * 64 + i * 16 + (lane >> 2);
#pragma unroll
                for (int jj = 0; jj < 8; ++jj) {
                    int col = wnl * 64 + jj * 8 + (lane & 3) * 2;
                    float* d = acc[i * 8 + jj];
                    *(float2*)&sf[row * 130 + col]       = make_float2(d[0], d[1]);
                    *(float2*)&sf[(row + 8) * 130 + col] = make_float2(d[2], d[3]);
                }
            }
        }
        __syncthreads();
        int pl = tid & 127, co2 = tid >> 7;
        float* yb = y + (size_t)nimg * 512 * HW + pbase + pl;
        int cb = co0 + pass * 128;
#pragma unroll 4
        for (int c = 0; c < 64; ++c) {
            int cl = c * 2 + co2;
            yb[(size_t)(cb + cl) * HW] = sf[pl * 130 + cl] + bias[cb + cl];
        }
    }
}

__global__ __launch_bounds__(256, 1) void conv_qkv_mma(
    const float* __restrict__ bq, const float* __restrict__ bk, const float* __restrict__ bv)
{
    int z = blockIdx.z;
    const float* bias = (z == 0) ? bq : (z == 1) ? bk : bv;
    float* y = (z == 0) ? g_y0 : (z == 1) ? g_y1 : g_y2;
    conv_mma_pipe(g_xh + (size_t)z * NELEM, g_xl + (size_t)z * NELEM,
                  g_Bh + (size_t)z * WSZ, g_Bl + (size_t)z * WSZ,
                  bias, y, 32, 8, 3, 8);
}

__global__ __launch_bounds__(256, 1) void conv_o_mma(const float* __restrict__ bo,
                                                     float* __restrict__ out)
{
    conv_mma_pipe(g_sah, g_sal, g_Bh + 3ull * WSZ, g_Bl + 3ull * WSZ,
                  bo, out, 8, 256, 8, 11);
}

// ---------------------------------------------------------------------------
// 3-stage cp.async pipelined GEMM: C(MxN) = A(MxK) * B(NxK)^T, hi/lo bf16
// CTA tile 128x128, warp tile 64x32.
// ---------------------------------------------------------------------------
__device__ __forceinline__ void gemm_mma_pipe(
    const __nv_bfloat16* __restrict__ Ah, const __nv_bfloat16* __restrict__ Al,
    const __nv_bfloat16* __restrict__ Bh, const __nv_bfloat16* __restrict__ Bl,
    int Kdim, int nchunk, float* __restrict__ C, int ldc)
{
    extern __shared__ char smem[];
    uint32_t sb = smem_u32(smem);
    int tid = threadIdx.x, wid = tid >> 5, lane = tid & 31;
    int m0 = blockIdx.y * 128, n0 = blockIdx.x * 128;
    int wm = wid & 1, wn = wid >> 1;

    int ar = tid >> 1, aseg = tid & 1;
    uint32_t rawb = (uint32_t)(ar * 128 + aseg * 64);
    const char* srcA_h = (const char*)(Ah + (size_t)(m0 + ar) * Kdim + aseg * 32);
    const char* srcA_l = (const char*)(Al + (size_t)(m0 + ar) * Kdim + aseg * 32);
    const char* srcB_h = (const char*)(Bh + (size_t)(n0 + ar) * Kdim + aseg * 32);
    const char* srcB_l = (const char*)(Bl + (size_t)(n0 + ar) * Kdim + aseg * 32);

    uint32_t a_rowb = (uint32_t)((wm * 64 + (lane & 15)) * 128) + ((lane & 16) ? 16u : 0u);
    uint32_t b_rowb = (uint32_t)((wn * 32 + (lane & 7) + ((lane & 16) ? 8 : 0)) * 128)
                    + ((lane & 8) ? 16u : 0u);

    float acc[16][4];
#pragma unroll
    for (int i = 0; i < 16; ++i)
#pragma unroll
        for (int j = 0; j < 4; ++j) acc[i][j] = 0.f;

    auto prefetch = [&](int itn, int stg) {
        int cb = itn * 128;
        uint32_t bs = sb + (uint32_t)stg * GSTAGE;
#pragma unroll
        for (int j = 0; j < 4; ++j) {
            uint32_t sw = SWZ(rawb + j * 16);
            CPA(bs + sw,          srcA_h + cb + j * 16, 16u);
            CPA(bs + 16384u + sw, srcA_l + cb + j * 16, 16u);
            CPA(bs + 32768u + sw, srcB_h + cb + j * 16, 16u);
            CPA(bs + 49152u + sw, srcB_l + cb + j * 16, 16u);
        }
        CPA_COMMIT();
    };

    prefetch(0, 0);
    prefetch(1, 1);
    int stg = 0;
    for (int it = 0; it < nchunk; ++it) {
        if (it < nchunk - 1) CPA_WAIT1(); else CPA_WAIT0();
        __syncthreads();
        if (it + 2 < nchunk) {
            int nst = stg + 2; if (nst >= 3) nst -= 3;
            prefetch(it + 2, nst);
        }
        mma_compute64(sb + (uint32_t)stg * GSTAGE, a_rowb, b_rowb, acc);
        if (++stg == 3) stg = 0;
    }

#pragma unroll
    for (int i = 0; i < 4; ++i) {
        int row = m0 + wm * 64 + i * 16 + (lane >> 2);
#pragma unroll
        for (int jj = 0; jj < 4; ++jj) {
            int col = n0 + wn * 32 + jj * 8 + (lane & 3) * 2;
            float* d = acc[i * 4 + jj];
            *(float2*)&C[(size_t)row * ldc + col]       = make_float2(d[0], d[1]);
            *(float2*)&C[(size_t)(row + 8) * ldc + col] = make_float2(d[2], d[3]);
        }
    }
}

__global__ __launch_bounds__(256, 1) void gemm_scores(float* __restrict__ attn)
{
    int nb = blockIdx.z;
    gemm_mma_pipe(g_Qh + (size_t)nb * 131072, g_Ql + (size_t)nb * 131072,
                  g_Kh + (size_t)nb * 131072, g_Kl + (size_t)nb * 131072,
                  256, 4, attn + (size_t)nb * 262144, 512);
}

__global__ __launch_bounds__(256, 1) void gemm_nnout()
{
    int nb = blockIdx.z;
    gemm_mma_pipe(g_ath + (size_t)nb * 262144, g_atl + (size_t)nb * 262144,
                  g_Vth + (size_t)nb * 131072, g_Vtl + (size_t)nb * 131072,
                  512, 8, g_On + (size_t)nb * 131072, 256);
}

// ---------------------------------------------------------------------------
// gather conv outputs into per-n bf16 hi/lo Q/K (row) and V (transposed)
// ---------------------------------------------------------------------------
__global__ void remap_qkvT()
{
    int t = blockIdx.x * 256 + threadIdx.x;
    int which = t >> 22;
    int e = t & (NELEM - 1);
    if (which == 2) {
        int n = e >> 17, c = (e >> 9) & 255, dk = e & 511;
        int h = c >> 5, r = c & 31;
        float v = g_y2[(h * 4 + (n >> 3)) * 131072 + ((n & 7) * 64 + (dk >> 3)) * 256
                       + (dk & 7) * 32 + r];
        __nv_bfloat16 hh = __float2bfloat16(v);
        g_Vth[e] = hh;
        g_Vtl[e] = __float2bfloat16(v - __bfloat162float(hh));
    } else {
        int n = e >> 17, d = (e >> 8) & 511, h = (e >> 5) & 7, r = e & 31;
        const float* src = which ? g_y1 : g_y0;
        float v = src[(h * 4 + (n >> 3)) * 131072 + ((n & 7) * 64 + (d >> 3)) * 256
                      + (d & 7) * 32 + r];
        __nv_bfloat16 hh = __float2bfloat16(v);
        __nv_bfloat16 ll = __float2bfloat16(v - __bfloat162float(hh));
        if (which) { g_Kh[e] = hh; g_Kl[e] = ll; }
        else       { g_Qh[e] = hh; g_Ql[e] = ll; }
    }
}

// ---------------------------------------------------------------------------
// softmax over 512-wide rows, in place; also emit bf16 hi/lo
// ---------------------------------------------------------------------------
__global__ void softmax_rows(float* __restrict__ attn)
{
    size_t base = (size_t)blockIdx.x * 512;
    float* p = attn + base;
    int tid = threadIdx.x;
    float v0 = p[tid], v1 = p[tid + 256];
    float m = fmaxf(v0, v1);
#pragma unroll
    for (int o = 16; o; o >>= 1) m = fmaxf(m, __shfl_xor_sync(~0u, m, o));
    __shared__ float sm[8], ss[8];
    if ((tid & 31) == 0) sm[tid >> 5] = m;
    __syncthreads();
    if (tid < 8) {
        float mm = sm[tid];
#pragma unroll
        for (int o = 4; o; o >>= 1) mm = fmaxf(mm, __shfl_xor_sync(0xffu, mm, o));
        if (tid == 0) sm[0] = mm;
    }
    __syncthreads();
    float M = sm[0];
    float e0 = expf(v0 - M), e1 = expf(v1 - M);
    float s = e0 + e1;
#pragma unroll
    for (int o = 16; o; o >>= 1) s += __shfl_xor_sync(~0u, s, o);
    if ((tid & 31) == 0) ss[tid >> 5] = s;
    __syncthreads();
    if (tid < 8) {
        float t2 = ss[tid];
#pragma unroll
        for (int o = 4; o; o >>= 1) t2 += __shfl_xor_sync(0xffu, t2, o);
        if (tid == 0) ss[0] = t2;
    }
    __syncthreads();
    float inv = 1.f / ss[0];
    float a0 = e0 * inv, a1 = e1 * inv;
    p[tid] = a0;
    p[tid + 256] = a1;
    __nv_bfloat16 h0 = __float2bfloat16(a0), h1 = __float2bfloat16(a1);
    g_ath[base + tid]       = h0;
    g_atl[base + tid]       = __float2bfloat16(a0 - __bfloat162float(h0));
    g_ath[base + tid + 256] = h1;
    g_atl[base + tid + 256] = __float2bfloat16(a1 - __bfloat162float(h1));
}

// ---------------------------------------------------------------------------
// scatter O into conv_o input, pixel-major bf16 hi/lo [b][p][ci]
// ---------------------------------------------------------------------------
__global__ void remap_sa_bf16()
{
    int e = blockIdx.x * 256 + threadIdx.x;
    int b  = e >> 20;
    int p  = (e >> 9) & 2047;
    int d2 = e & 511;
    int s  = p >> 8;
    int rh = p & 255;
    int r2 = rh >> 3, h2 = rh & 7;
    int n  = b * 8 + s;
    int qd = r2 * 16 + h2 * 2 + (d2 >> 8);
    int rr = (d2 & 255) >> 3;
    int hh = d2 & 7;
    float v = g_On[n * 131072 + qd * 256 + hh * 32 + rr];
    __nv_bfloat16 h = __float2bfloat16(v);
    g_sah[e] = h;
    g_sal[e] = __float2bfloat16(v - __bfloat162float(h));
}

// ---------------------------------------------------------------------------
extern "C" void kernel_launch(void* const* d_in, const int* in_sizes, int n_in,
                              void* d_out, int out_size)
{
    const float* q  = (const float*)d_in[0];
    const float* k  = (const float*)d_in[1];
    const float* v  = (const float*)d_in[2];
    const float* Wq = (const float*)d_in[3];
    const float* bq = (const float*)d_in[4];
    const float* Wk = (const float*)d_in[5];
    const float* bk = (const float*)d_in[6];
    const float* Wv = (const float*)d_in[7];
    const float* bv = (const float*)d_in[8];
    const float* Wo = (const float*)d_in[9];
    const float* bo = (const float*)d_in[10];

    float* y_out    = (float*)d_out;            // (4,512,8,32,8) = 4194304
    float* attn_out = y_out + NELEM;            // (1,32,512,512) = 8388608

    cudaFuncSetAttribute(conv_qkv_mma, cudaFuncAttributeMaxDynamicSharedMemorySize, SMEM_BYTES);
    cudaFuncSetAttribute(conv_o_mma,   cudaFuncAttributeMaxDynamicSharedMemorySize, SMEM_BYTES);
    cudaFuncSetAttribute(gemm_scores,  cudaFuncAttributeMaxDynamicSharedMemorySize, SMEM_BYTES);
    cudaFuncSetAttribute(gemm_nnout,   cudaFuncAttributeMaxDynamicSharedMemorySize, SMEM_BYTES);

    // launch order arranged so the ncu capture (launch index 3) hits conv_qkv_mma
    prep_w<<<4 * WSZ / 256, 256>>>(Wq, Wk, Wv, Wo);                 // 0
    prep_x<<<dim3(8, 16, 64), dim3(32, 8)>>>(q, k, v, 0);           // 1
    prep_x<<<dim3(8, 16, 32), dim3(32, 8)>>>(q, k, v, 64);          // 2
    conv_qkv_mma<<<dim3(64, 2, 3), 256, SMEM_BYTES>>>(bq, bk, bv);  // 3  <- profiled
    remap_qkvT<<<3 * NELEM / 256, 256>>>();                         // 4
    gemm_scores<<<dim3(4, 4, 32), 256, SMEM_BYTES>>>(attn_out);     // 5
    softmax_rows<<<32 * 512, 256>>>(attn_out);                      // 6
    gemm_nnout<<<dim3(2, 4, 32), 256, SMEM_BYTES>>>();              // 7
    remap_sa_bf16<<<NELEM / 256, 256>>>();                          // 8
    conv_o_mma<<<dim3(64, 2, 1), 256, SMEM_BYTES>>>(bo, y_out);     // 9
}

// round 6
// speedup vs baseline: 1.1903x; 1.1903x over previous
#include <cuda_runtime.h>
#include <cuda_bf16.h>
#include <cstdint>

#define NELEM 4194304          // 32*512*32*8 == 4*512*8*256
#define WSZ   2359296          // 512*4608 weight elements per conv

// ---------------------------------------------------------------------------
// device scratch
// ---------------------------------------------------------------------------
__device__ __nv_bfloat16 g_Bh[4*WSZ];   // weights hi  [conv][co][t*512+ci]
__device__ __nv_bfloat16 g_Bl[4*WSZ];   // weights lo
__device__ __nv_bfloat16 g_xh[3*NELEM]; // qkv inputs hi, pixel-major [z][n][p][ci]
__device__ __nv_bfloat16 g_xl[3*NELEM];
__device__ __nv_bfloat16 g_sah[NELEM];  // conv_o input hi [b][p][ci]
__device__ __nv_bfloat16 g_sal[NELEM];
__device__ float g_y0[NELEM];           // conv(q) out (32,512,32,8)
__device__ float g_y1[NELEM];
__device__ float g_y2[NELEM];
__device__ __nv_bfloat16 g_Qh[NELEM], g_Ql[NELEM];   // [n][d][c], c=h*32+r
__device__ __nv_bfloat16 g_Kh[NELEM], g_Kl[NELEM];
__device__ __nv_bfloat16 g_Vth[NELEM], g_Vtl[NELEM]; // transposed: [n][c][dk]
__device__ __nv_bfloat16 g_ath[2*NELEM], g_atl[2*NELEM]; // attn hi/lo
__device__ float g_On[NELEM];           // attn @ V  [n][qd][c]

// ---------------------------------------------------------------------------
// helpers
// ---------------------------------------------------------------------------
__device__ __forceinline__ uint32_t smem_u32(const void* p) {
    uint32_t a;
    asm("{ .reg .u64 t; cvta.to.shared.u64 t, %1; cvt.u32.u64 %0, t; }" : "=r"(a) : "l"(p));
    return a;
}
#define SWZ(o) ((o) ^ (((o) >> 3) & 0x70))
#define CPA(dst, src, sz) \
    asm volatile("cp.async.cg.shared.global [%0], [%1], 16, %2;" \
        :: "r"(dst), "l"(src), "r"(sz) : "memory")
#define CPA_COMMIT() asm volatile("cp.async.commit_group;" ::: "memory")
#define CPA_WAIT1()  asm volatile("cp.async.wait_group 1;" ::: "memory")
#define CPA_WAIT0()  asm volatile("cp.async.wait_group 0;" ::: "memory")
#define LDM4(r, addr) \
    asm volatile("ldmatrix.sync.aligned.m8n8.x4.shared.b16 {%0,%1,%2,%3}, [%4];" \
        : "=r"((r)[0]), "=r"((r)[1]), "=r"((r)[2]), "=r"((r)[3]) : "r"(addr))
#define MMA_BF16(d, a, b0, b1) \
    asm volatile("mma.sync.aligned.m16n8k16.row.col.f32.bf16.bf16.f32 " \
        "{%0,%1,%2,%3}, {%4,%5,%6,%7}, {%8,%9}, {%0,%1,%2,%3};" \
        : "+f"((d)[0]), "+f"((d)[1]), "+f"((d)[2]), "+f"((d)[3]) \
        : "r"((a)[0]), "r"((a)[1]), "r"((a)[2]), "r"((a)[3]), "r"(b0), "r"(b1))

// K32 chunk; packed layout: two 64B K-rows per 128B line.
// stage (32KB): Ah 0, Al 8K, Bh 16K, Bl 24K. 3 stages = 96KB -> 2 CTAs/SM.
#define STAGE 32768u
#define SMEM_BYTES 98304

// packed row base (bytes) for logical row r with 64B rows
#define PROW(r) ((uint32_t)((((r) >> 1) << 7) | (((r) & 1) << 6)))

// ---------------------------------------------------------------------------
// compute one K32 chunk, warp tile 64x32: D += Ah*Bh + Ah*Bl + Al*Bh
// ---------------------------------------------------------------------------
__device__ __forceinline__ void mma_compute32(uint32_t bs, uint32_t a_rowb,
                                              uint32_t b_rowb, float (&acc)[16][4])
{
#pragma unroll
    for (int s = 0; s < 2; ++s) {
        uint32_t ah[4][4], bb[2][4], blf[2][4];
#pragma unroll
        for (int i = 0; i < 4; ++i)
            LDM4(ah[i], bs + SWZ(a_rowb + i * 1024 + s * 32));
#pragma unroll
        for (int j = 0; j < 2; ++j)
            LDM4(bb[j], bs + 16384u + SWZ(b_rowb + j * 1024 + s * 32));
#pragma unroll
        for (int i = 0; i < 4; ++i)
#pragma unroll
            for (int jj = 0; jj < 4; ++jj)
                MMA_BF16(acc[i * 4 + jj], ah[i],
                         bb[jj >> 1][(jj & 1) * 2], bb[jj >> 1][(jj & 1) * 2 + 1]);
#pragma unroll
        for (int j = 0; j < 2; ++j)
            LDM4(blf[j], bs + 24576u + SWZ(b_rowb + j * 1024 + s * 32));
#pragma unroll
        for (int i = 0; i < 4; ++i)
#pragma unroll
            for (int jj = 0; jj < 4; ++jj)
                MMA_BF16(acc[i * 4 + jj], ah[i],
                         blf[jj >> 1][(jj & 1) * 2], blf[jj >> 1][(jj & 1) * 2 + 1]);
#pragma unroll
        for (int i = 0; i < 4; ++i)
            LDM4(ah[i], bs + 8192u + SWZ(a_rowb + i * 1024 + s * 32));
#pragma unroll
        for (int i = 0; i < 4; ++i)
#pragma unroll
            for (int jj = 0; jj < 4; ++jj)
                MMA_BF16(acc[i * 4 + jj], ah[i],
                         bb[jj >> 1][(jj & 1) * 2], bb[jj >> 1][(jj & 1) * 2 + 1]);
    }
}

// ---------------------------------------------------------------------------
// pre-pass: weights -> bf16 hi/lo in [co][t*512+ci] layout
// ---------------------------------------------------------------------------
__global__ void prep_w(const float* __restrict__ Wq, const float* __restrict__ Wk,
                       const float* __restrict__ Wv, const float* __restrict__ Wo)
{
    int g = blockIdx.x * 256 + threadIdx.x;
    int conv = g / WSZ;
    int j = g - conv * WSZ;
    const float* W = (conv == 0) ? Wq : (conv == 1) ? Wk : (conv == 2) ? Wv : Wo;
    float v = W[j];
    int co  = j / 4608;
    int rem = j - co * 4608;
    int ci  = rem / 9;
    int t   = rem - ci * 9;
    __nv_bfloat16 h = __float2bfloat16(v);
    __nv_bfloat16 l = __float2bfloat16(v - __bfloat162float(h));
    size_t o = (size_t)conv * WSZ + (size_t)co * 4608 + t * 512 + ci;
    g_Bh[o] = h;
    g_Bl[o] = l;
}

// ---------------------------------------------------------------------------
// pre-pass: q/k/v (32 imgs, 512 ch, 256 pix) -> pixel-major bf16 hi/lo
// ---------------------------------------------------------------------------
__global__ void prep_x(const float* __restrict__ q, const float* __restrict__ k,
                       const float* __restrict__ v, int zoff)
{
    __shared__ float tile[32][33];
    int zz = blockIdx.z + zoff;
    int z = zz >> 5;
    int n = zz & 31;
    const float* src = (z == 0) ? q : (z == 1) ? k : v;
    const float* xin = src + (size_t)n * 512 * 256;
    __nv_bfloat16* oh = g_xh + (size_t)z * NELEM + (size_t)n * 256 * 512;
    __nv_bfloat16* ol = g_xl + (size_t)z * NELEM + (size_t)n * 256 * 512;
    int p0 = blockIdx.x * 32;
    int c0 = blockIdx.y * 32;
    int tx = threadIdx.x, ty = threadIdx.y;
#pragma unroll
    for (int j = 0; j < 4; ++j)
        tile[ty + 8 * j][tx] = xin[(size_t)(c0 + ty + 8 * j) * 256 + p0 + tx];
    __syncthreads();
#pragma unroll
    for (int j = 0; j < 4; ++j) {
        float val = tile[tx][ty + 8 * j];
        __nv_bfloat16 h = __float2bfloat16(val);
        size_t o = (size_t)(p0 + ty + 8 * j) * 512 + c0 + tx;
        oh[o] = h;
        ol[o] = __float2bfloat16(val - __bfloat162float(h));
    }
}

// ---------------------------------------------------------------------------
// 3-stage cp.async pipelined implicit-GEMM conv. M=128 pix x N=128 co.
// 8 warps (2 x 4), warp tile 64x32. K in 144 chunks of 32 (tap-major).
// 2 CTAs/SM for cross-CTA latency hiding.
// ---------------------------------------------------------------------------
__device__ __forceinline__ void conv_mma_pipe(
    const __nv_bfloat16* __restrict__ xh, const __nv_bfloat16* __restrict__ xl,
    const __nv_bfloat16* __restrict__ bh, const __nv_bfloat16* __restrict__ bl,
    const float* __restrict__ bias, float* __restrict__ y,
    int H, int W, int logW, int logPIX)
{
    extern __shared__ char smem[];
    uint32_t sb = smem_u32(smem);
    int tid = threadIdx.x, wid = tid >> 5, lane = tid & 31;
    const int HW = 1 << logPIX;
    int p0    = blockIdx.x * 128;
    int nimg  = p0 >> logPIX;
    int pbase = p0 & (HW - 1);
    int co0   = blockIdx.y * 128;
    int wm = wid & 1, wn = wid >> 1;

    // loader: thread -> (row = tid>>1, 32B half = tid&1)
    int lr = tid >> 1, lh = tid & 1;
    int ap = pbase + lr;
    int ayr = ap >> logW, axr = ap & (W - 1);
    uint32_t stb = PROW(lr) + lh * 32u;                 // packed store base
    const __nv_bfloat16* arow_h = xh + (size_t)nimg * HW * 512 + lh * 16;
    const __nv_bfloat16* arow_l = xl + (size_t)nimg * HW * 512 + lh * 16;
    const __nv_bfloat16* brow_h = bh + (size_t)(co0 + lr) * 4608 + lh * 16;
    const __nv_bfloat16* brow_l = bl + (size_t)(co0 + lr) * 4608 + lh * 16;

    // ldmatrix lane geometry (packed rows)
    int arow = wm * 64 + (lane & 15);
    uint32_t a_rowb = PROW(arow) + ((lane & 16) ? 16u : 0u);
    int brow = wn * 32 + (lane & 7) + ((lane & 16) ? 8 : 0);
    uint32_t b_rowb = PROW(brow) + ((lane & 8) ? 16u : 0u);

    float acc[16][4];
#pragma unroll
    for (int i = 0; i < 16; ++i)
#pragma unroll
        for (int j = 0; j < 4; ++j) acc[i][j] = 0.f;

    auto prefetch = [&](int itn, int stg) {
        int t = itn >> 4, ci0 = (itn & 15) << 5;        // 16 K32 chunks per tap
        int q3 = (t * 11) >> 5;                         // t/3 for t in [0,9)
        int dy = q3 - 1, dx = t - q3 * 3 - 1;
        int yy = ayr + dy, xx = axr + dx;
        bool ok = ((unsigned)yy < (unsigned)H) && ((unsigned)xx < (unsigned)W);
        int pps = ok ? ((yy << logW) + xx) : 0;
        const char* sAh = (const char*)(arow_h + (size_t)pps * 512 + ci0);
        const char* sAl = (const char*)(arow_l + (size_t)pps * 512 + ci0);
        const char* sBh = (const char*)(brow_h + t * 512 + ci0);
        const char* sBl = (const char*)(brow_l + t * 512 + ci0);
        uint32_t bs = sb + (uint32_t)stg * STAGE;
        uint32_t asz = ok ? 16u : 0u;
        uint32_t s0 = SWZ(stb), s1 = SWZ(stb + 16u);
        CPA(bs + s0,           sAh,      asz);
        CPA(bs + s1,           sAh + 16, asz);
        CPA(bs + 8192u + s0,   sAl,      asz);
        CPA(bs + 8192u + s1,   sAl + 16, asz);
        CPA(bs + 16384u + s0,  sBh,      16u);
        CPA(bs + 16384u + s1,  sBh + 16, 16u);
        CPA(bs + 24576u + s0,  sBl,      16u);
        CPA(bs + 24576u + s1,  sBl + 16, 16u);
        CPA_COMMIT();
    };

    prefetch(0, 0);
    prefetch(1, 1);
    int stg = 0;
    for (int it = 0; it < 144; ++it) {
        if (it < 143) CPA_WAIT1(); else CPA_WAIT0();
        __syncthreads();
        if (it + 2 < 144) {
            int nst = stg + 2; if (nst >= 3) nst -= 3;
            prefetch(it + 2, nst);
        }
        mma_compute32(sb + (uint32_t)stg * STAGE, a_rowb, b_rowb, acc);
        if (++stg == 3) stg = 0;
    }
    __syncthreads();

    // epilogue: stage via SMEM (128 x 130 fp32) for coalesced [co][pix] stores
    float* sf = (float*)smem;
#pragma unroll
    for (int i = 0; i < 4; ++i) {
        int row = wm * 64 + i * 16 + (lane >> 2);
#pragma unroll
        for (int jj = 0; jj < 4; ++jj) {
            int col = wn * 32 + jj * 8 + (lane & 3) * 2;
            float* d = acc[i * 4 + jj];
            *(float2*)&sf[row * 130 + col]       = make_float2(d[0], d[1]);
            *(float2*)&sf[(row + 8) * 130 + col] = make_float2(d[2], d[3]);
        }
    }
    __syncthreads();
    {
        int pl = tid & 127, co2 = tid >> 7;
        float* yb = y + (size_t)nimg * 512 * HW + pbase + pl;
#pragma unroll 4
        for (int c = 0; c < 64; ++c) {
            int cl = c * 2 + co2;
            yb[(size_t)(co0 + cl) * HW] = sf[pl * 130 + cl] + bias[co0 + cl];
        }
    }
}

__global__ __launch_bounds__(256, 2) void conv_qkv_mma(
    const float* __restrict__ bq, const float* __restrict__ bk, const float* __restrict__ bv)
{
    int z = blockIdx.z;
    const float* bias = (z == 0) ? bq : (z == 1) ? bk : bv;
    float* y = (z == 0) ? g_y0 : (z == 1) ? g_y1 : g_y2;
    conv_mma_pipe(g_xh + (size_t)z * NELEM, g_xl + (size_t)z * NELEM,
                  g_Bh + (size_t)z * WSZ, g_Bl + (size_t)z * WSZ,
                  bias, y, 32, 8, 3, 8);
}

__global__ __launch_bounds__(256, 2) void conv_o_mma(const float* __restrict__ bo,
                                                     float* __restrict__ out)
{
    conv_mma_pipe(g_sah, g_sal, g_Bh + 3ull * WSZ, g_Bl + 3ull * WSZ,
                  bo, out, 8, 256, 8, 11);
}

// ---------------------------------------------------------------------------
// 3-stage cp.async pipelined GEMM: C(MxN) = A(MxK) * B(NxK)^T, hi/lo bf16
// CTA tile 128x128, warp tile 64x32, K32 chunks, 2 CTAs/SM.
// ---------------------------------------------------------------------------
__device__ __forceinline__ void gemm_mma_pipe(
    const __nv_bfloat16* __restrict__ Ah, const __nv_bfloat16* __restrict__ Al,
    const __nv_bfloat16* __restrict__ Bh, const __nv_bfloat16* __restrict__ Bl,
    int Kdim, int nchunk, float* __restrict__ C, int ldc)
{
    extern __shared__ char smem[];
    uint32_t sb = smem_u32(smem);
    int tid = threadIdx.x, wid = tid >> 5, lane = tid & 31;
    int m0 = blockIdx.y * 128, n0 = blockIdx.x * 128;
    int wm = wid & 1, wn = wid >> 1;

    int lr = tid >> 1, lh = tid & 1;
    uint32_t stb = PROW(lr) + lh * 32u;
    const char* srcA_h = (const char*)(Ah + (size_t)(m0 + lr) * Kdim + lh * 16);
    const char* srcA_l = (const char*)(Al + (size_t)(m0 + lr) * Kdim + lh * 16);
    const char* srcB_h = (const char*)(Bh + (size_t)(n0 + lr) * Kdim + lh * 16);
    const char* srcB_l = (const char*)(Bl + (size_t)(n0 + lr) * Kdim + lh * 16);

    int arow = wm * 64 + (lane & 15);
    uint32_t a_rowb = PROW(arow) + ((lane & 16) ? 16u : 0u);
    int brow = wn * 32 + (lane & 7) + ((lane & 16) ? 8 : 0);
    uint32_t b_rowb = PROW(brow) + ((lane & 8) ? 16u : 0u);

    float acc[16][4];
#pragma unroll
    for (int i = 0; i < 16; ++i)
#pragma unroll
        for (int j = 0; j < 4; ++j) acc[i][j] = 0.f;

    auto prefetch = [&](int itn, int stg) {
        int cb = itn * 64;                  // bytes along K (32 bf16)
        uint32_t bs = sb + (uint32_t)stg * STAGE;
        uint32_t s0 = SWZ(stb), s1 = SWZ(stb + 16u);
        CPA(bs + s0,          srcA_h + cb,      16u);
        CPA(bs + s1,          srcA_h + cb + 16, 16u);
        CPA(bs + 8192u + s0,  srcA_l + cb,      16u);
        CPA(bs + 8192u + s1,  srcA_l + cb + 16, 16u);
        CPA(bs + 16384u + s0, srcB_h + cb,      16u);
        CPA(bs + 16384u + s1, srcB_h + cb + 16, 16u);
        CPA(bs + 24576u + s0, srcB_l + cb,      16u);
        CPA(bs + 24576u + s1, srcB_l + cb + 16, 16u);
        CPA_COMMIT();
    };

    prefetch(0, 0);
    prefetch(1, 1);
    int stg = 0;
    for (int it = 0; it < nchunk; ++it) {
        if (it < nchunk - 1) CPA_WAIT1(); else CPA_WAIT0();
        __syncthreads();
        if (it + 2 < nchunk) {
            int nst = stg + 2; if (nst >= 3) nst -= 3;
            prefetch(it + 2, nst);
        }
        mma_compute32(sb + (uint32_t)stg * STAGE, a_rowb, b_rowb, acc);
        if (++stg == 3) stg = 0;
    }

#pragma unroll
    for (int i = 0; i < 4; ++i) {
        int row = m0 + wm * 64 + i * 16 + (lane >> 2);
#pragma unroll
        for (int jj = 0; jj < 4; ++jj) {
            int col = n0 + wn * 32 + jj * 8 + (lane & 3) * 2;
            float* d = acc[i * 4 + jj];
            *(float2*)&C[(size_t)row * ldc + col]       = make_float2(d[0], d[1]);
            *(float2*)&C[(size_t)(row + 8) * ldc + col] = make_float2(d[2], d[3]);
        }
    }
}

__global__ __launch_bounds__(256, 2) void gemm_scores(float* __restrict__ attn)
{
    int nb = blockIdx.z;
    gemm_mma_pipe(g_Qh + (size_t)nb * 131072, g_Ql + (size_t)nb * 131072,
                  g_Kh + (size_t)nb * 131072, g_Kl + (size_t)nb * 131072,
                  256, 8, attn + (size_t)nb * 262144, 512);
}

__global__ __launch_bounds__(256, 2) void gemm_nnout()
{
    int nb = blockIdx.z;
    gemm_mma_pipe(g_ath + (size_t)nb * 262144, g_atl + (size_t)nb * 262144,
                  g_Vth + (size_t)nb * 131072, g_Vtl + (size_t)nb * 131072,
                  512, 16, g_On + (size_t)nb * 131072, 256);
}

// ---------------------------------------------------------------------------
// gather conv outputs into per-n bf16 hi/lo Q/K (row) and V (transposed)
// ---------------------------------------------------------------------------
__global__ void remap_qkvT()
{
    int t = blockIdx.x * 256 + threadIdx.x;
    int which = t >> 22;
    int e = t & (NELEM - 1);
    if (which == 2) {
        int n = e >> 17, c = (e >> 9) & 255, dk = e & 511;
        int h = c >> 5, r = c & 31;
        float v = g_y2[(h * 4 + (n >> 3)) * 131072 + ((n & 7) * 64 + (dk >> 3)) * 256
                       + (dk & 7) * 32 + r];
        __nv_bfloat16 hh = __float2bfloat16(v);
        g_Vth[e] = hh;
        g_Vtl[e] = __float2bfloat16(v - __bfloat162float(hh));
    } else {
        int n = e >> 17, d = (e >> 8) & 511, h = (e >> 5) & 7, r = e & 31;
        const float* src = which ? g_y1 : g_y0;
        float v = src[(h * 4 + (n >> 3)) * 131072 + ((n & 7) * 64 + (d >> 3)) * 256
                      + (d & 7) * 32 + r];
        __nv_bfloat16 hh = __float2bfloat16(v);
        __nv_bfloat16 ll = __float2bfloat16(v - __bfloat162float(hh));
        if (which) { g_Kh[e] = hh; g_Kl[e] = ll; }
        else       { g_Qh[e] = hh; g_Ql[e] = ll; }
    }
}

// ---------------------------------------------------------------------------
// softmax over 512-wide rows, in place; also emit bf16 hi/lo
// ---------------------------------------------------------------------------
__global__ void softmax_rows(float* __restrict__ attn)
{
    size_t base = (size_t)blockIdx.x * 512;
    float* p = attn + base;
    int tid = threadIdx.x;
    float v0 = p[tid], v1 = p[tid + 256];
    float m = fmaxf(v0, v1);
#pragma unroll
    for (int o = 16; o; o >>= 1) m = fmaxf(m, __shfl_xor_sync(~0u, m, o));
    __shared__ float sm[8], ss[8];
    if ((tid & 31) == 0) sm[tid >> 5] = m;
    __syncthreads();
    if (tid < 8) {
        float mm = sm[tid];
#pragma unroll
        for (int o = 4; o; o >>= 1) mm = fmaxf(mm, __shfl_xor_sync(0xffu, mm, o));
        if (tid == 0) sm[0] = mm;
    }
    __syncthreads();
    float M = sm[0];
    float e0 = expf(v0 - M), e1 = expf(v1 - M);
    float s = e0 + e1;
#pragma unroll
    for (int o = 16; o; o >>= 1) s += __shfl_xor_sync(~0u, s, o);
    if ((tid & 31) == 0) ss[tid >> 5] = s;
    __syncthreads();
    if (tid < 8) {
        float t2 = ss[tid];
#pragma unroll
        for (int o = 4; o; o >>= 1) t2 += __shfl_xor_sync(0xffu, t2, o);
        if (tid == 0) ss[0] = t2;
    }
    __syncthreads();
    float inv = 1.f / ss[0];
    float a0 = e0 * inv, a1 = e1 * inv;
    p[tid] = a0;
    p[tid + 256] = a1;
    __nv_bfloat16 h0 = __float2bfloat16(a0), h1 = __float2bfloat16(a1);
    g_ath[base + tid]       = h0;
    g_atl[base + tid]       = __float2bfloat16(a0 - __bfloat162float(h0));
    g_ath[base + tid + 256] = h1;
    g_atl[base + tid + 256] = __float2bfloat16(a1 - __bfloat162float(h1));
}

// ---------------------------------------------------------------------------
// scatter O into conv_o input, pixel-major bf16 hi/lo [b][p][ci]
// ---------------------------------------------------------------------------
__global__ void remap_sa_bf16()
{
    int e = blockIdx.x * 256 + threadIdx.x;
    int b  = e >> 20;
    int p  = (e >> 9) & 2047;
    int d2 = e & 511;
    int s  = p >> 8;
    int rh = p & 255;
    int r2 = rh >> 3, h2 = rh & 7;
    int n  = b * 8 + s;
    int qd = r2 * 16 + h2 * 2 + (d2 >> 8);
    int rr = (d2 & 255) >> 3;
    int hh = d2 & 7;
    float v = g_On[n * 131072 + qd * 256 + hh * 32 + rr];
    __nv_bfloat16 h = __float2bfloat16(v);
    g_sah[e] = h;
    g_sal[e] = __float2bfloat16(v - __bfloat162float(h));
}

// ---------------------------------------------------------------------------
extern "C" void kernel_launch(void* const* d_in, const int* in_sizes, int n_in,
                              void* d_out, int out_size)
{
    const float* q  = (const float*)d_in[0];
    const float* k  = (const float*)d_in[1];
    const float* v  = (const float*)d_in[2];
    const float* Wq = (const float*)d_in[3];
    const float* bq = (const float*)d_in[4];
    const float* Wk = (const float*)d_in[5];
    const float* bk = (const float*)d_in[6];
    const float* Wv = (const float*)d_in[7];
    const float* bv = (const float*)d_in[8];
    const float* Wo = (const float*)d_in[9];
    const float* bo = (const float*)d_in[10];

    float* y_out    = (float*)d_out;            // (4,512,8,32,8) = 4194304
    float* attn_out = y_out + NELEM;            // (1,32,512,512) = 8388608

    cudaFuncSetAttribute(conv_qkv_mma, cudaFuncAttributeMaxDynamicSharedMemorySize, SMEM_BYTES);
    cudaFuncSetAttribute(conv_o_mma,   cudaFuncAttributeMaxDynamicSharedMemorySize, SMEM_BYTES);
    cudaFuncSetAttribute(gemm_scores,  cudaFuncAttributeMaxDynamicSharedMemorySize, SMEM_BYTES);
    cudaFuncSetAttribute(gemm_nnout,   cudaFuncAttributeMaxDynamicSharedMemorySize, SMEM_BYTES);

    // launch order arranged so the ncu capture (launch index 3) hits conv_qkv_mma
    prep_w<<<4 * WSZ / 256, 256>>>(Wq, Wk, Wv, Wo);                 // 0
    prep_x<<<dim3(8, 16, 64), dim3(32, 8)>>>(q, k, v, 0);           // 1
    prep_x<<<dim3(8, 16, 32), dim3(32, 8)>>>(q, k, v, 64);          // 2
    conv_qkv_mma<<<dim3(64, 4, 3), 256, SMEM_BYTES>>>(bq, bk, bv);  // 3  <- profiled
    remap_qkvT<<<3 * NELEM / 256, 256>>>();                         // 4
    gemm_scores<<<dim3(4, 4, 32), 256, SMEM_BYTES>>>(attn_out);     // 5
    softmax_rows<<<32 * 512, 256>>>(attn_out);                      // 6
    gemm_nnout<<<dim3(2, 4, 32), 256, SMEM_BYTES>>>();              // 7
    remap_sa_bf16<<<NELEM / 256, 256>>>();                          // 8
    conv_o_mma<<<dim3(64, 4, 1), 256, SMEM_BYTES>>>(bo, y_out);     // 9
}